// round 1
// baseline (speedup 1.0000x reference)
#include <cuda_runtime.h>
#include <math.h>

#define B_   32
#define N_   256
#define E_   512
#define H_   8
#define D_   64
#define ID_  8
#define KDIM 512

// ---------------- device-global scratch (alloc-free) ----------------
__device__ float g_q[(size_t)B_*H_*N_*D_];      // 16 MB, pre-scaled by D^-0.5
__device__ float g_k[(size_t)B_*H_*N_*D_];      // 16 MB
__device__ float g_v[(size_t)B_*H_*N_*D_];      // 16 MB
__device__ float g_bias[(size_t)B_*H_*N_*N_];   // 64 MB
__device__ float g_o[(size_t)B_*N_*E_];         // 16 MB

// ---------------- bias = U @ w_u^T + b_u, transposed to [B,H,N,N] ----------------
__global__ void bias_kernel(const float* __restrict__ U,
                            const float* __restrict__ w_u,
                            const float* __restrict__ b_u) {
    __shared__ float sw[H_*ID_];
    __shared__ float sb[H_];
    if (threadIdx.x < H_*ID_) sw[threadIdx.x] = w_u[threadIdx.x];
    if (threadIdx.x < H_)     sb[threadIdx.x] = b_u[threadIdx.x];
    __syncthreads();
    int idx = blockIdx.x * blockDim.x + threadIdx.x;     // over B*N*N
    if (idx >= B_*N_*N_) return;
    const float4* up = (const float4*)(U + (size_t)idx * ID_);
    float4 u0 = up[0], u1 = up[1];
    float u[8] = {u0.x,u0.y,u0.z,u0.w,u1.x,u1.y,u1.z,u1.w};
    int b  = idx / (N_*N_);
    int nm = idx - b * (N_*N_);
    #pragma unroll
    for (int h = 0; h < H_; h++) {
        float s = sb[h];
        #pragma unroll
        for (int i = 0; i < 8; i++) s += u[i] * sw[h*ID_ + i];
        g_bias[((size_t)(b*H_ + h)) * (N_*N_) + nm] = s;
    }
}

// ---------------- SGEMM: C[M,NC] = A[M,K] * W[NC,K]^T  (128x128x16, 8x8/thr) ----------------
// Epilogue 1 (QKV): scatter to g_q/g_k/g_v in [B,H,N,D] layout; q scaled by 0.125.
__global__ void qkv_gemm(const float* __restrict__ A,
                         const float* __restrict__ W,
                         const float* __restrict__ bias) {
    __shared__ float As[16*128];
    __shared__ float Bs[16*128];
    const int t = threadIdx.x;
    const int rowBase = blockIdx.y * 128;
    const int colBase = blockIdx.x * 128;
    const int ty = t >> 4, tx = t & 15;
    float acc[8][8];
    #pragma unroll
    for (int i = 0; i < 8; i++)
        #pragma unroll
        for (int j = 0; j < 8; j++) acc[i][j] = 0.f;

    for (int k0 = 0; k0 < KDIM; k0 += 16) {
        #pragma unroll
        for (int l = 0; l < 2; l++) {
            int f   = t + l*256;         // 512 float4s per 128x16 tile
            int ar  = f >> 2;
            int ac4 = (f & 3) * 4;
            float4 av = *(const float4*)(A + (size_t)(rowBase+ar)*KDIM + k0 + ac4);
            As[(ac4+0)*128+ar]=av.x; As[(ac4+1)*128+ar]=av.y;
            As[(ac4+2)*128+ar]=av.z; As[(ac4+3)*128+ar]=av.w;
            float4 wv = *(const float4*)(W + (size_t)(colBase+ar)*KDIM + k0 + ac4);
            Bs[(ac4+0)*128+ar]=wv.x; Bs[(ac4+1)*128+ar]=wv.y;
            Bs[(ac4+2)*128+ar]=wv.z; Bs[(ac4+3)*128+ar]=wv.w;
        }
        __syncthreads();
        #pragma unroll
        for (int k = 0; k < 16; k++) {
            float a[8], b[8];
            #pragma unroll
            for (int i = 0; i < 8; i++) a[i] = As[k*128 + ty + i*16];
            #pragma unroll
            for (int j = 0; j < 8; j++) b[j] = Bs[k*128 + tx + j*16];
            #pragma unroll
            for (int i = 0; i < 8; i++)
                #pragma unroll
                for (int j = 0; j < 8; j++) acc[i][j] += a[i]*b[j];
        }
        __syncthreads();
    }
    // epilogue: route column c -> (q|k|v)[b,h,n,d]
    #pragma unroll
    for (int i = 0; i < 8; i++) {
        int row = rowBase + ty + i*16;
        int bb = row >> 8;        // /N_
        int n  = row & 255;
        #pragma unroll
        for (int j = 0; j < 8; j++) {
            int c = colBase + tx + j*16;
            float val = acc[i][j] + __ldg(bias + c);
            int sec = c >> 9;     // 0=q 1=k 2=v
            int jj  = c & 511;
            int h   = jj >> 6, d = jj & 63;
            size_t dst = ((size_t)((bb*H_ + h)*N_ + n))*D_ + d;
            if      (sec == 0) g_q[dst] = val * 0.125f;
            else if (sec == 1) g_k[dst] = val;
            else               g_v[dst] = val;
        }
    }
}

// Epilogue 2 (out proj): A = g_o, write final output.
__global__ void out_gemm(const float* __restrict__ W,
                         const float* __restrict__ bias,
                         float* __restrict__ out) {
    __shared__ float As[16*128];
    __shared__ float Bs[16*128];
    const int t = threadIdx.x;
    const int rowBase = blockIdx.y * 128;
    const int colBase = blockIdx.x * 128;
    const int ty = t >> 4, tx = t & 15;
    float acc[8][8];
    #pragma unroll
    for (int i = 0; i < 8; i++)
        #pragma unroll
        for (int j = 0; j < 8; j++) acc[i][j] = 0.f;

    const float* A = g_o;
    for (int k0 = 0; k0 < KDIM; k0 += 16) {
        #pragma unroll
        for (int l = 0; l < 2; l++) {
            int f   = t + l*256;
            int ar  = f >> 2;
            int ac4 = (f & 3) * 4;
            float4 av = *(const float4*)(A + (size_t)(rowBase+ar)*KDIM + k0 + ac4);
            As[(ac4+0)*128+ar]=av.x; As[(ac4+1)*128+ar]=av.y;
            As[(ac4+2)*128+ar]=av.z; As[(ac4+3)*128+ar]=av.w;
            float4 wv = *(const float4*)(W + (size_t)(colBase+ar)*KDIM + k0 + ac4);
            Bs[(ac4+0)*128+ar]=wv.x; Bs[(ac4+1)*128+ar]=wv.y;
            Bs[(ac4+2)*128+ar]=wv.z; Bs[(ac4+3)*128+ar]=wv.w;
        }
        __syncthreads();
        #pragma unroll
        for (int k = 0; k < 16; k++) {
            float a[8], b[8];
            #pragma unroll
            for (int i = 0; i < 8; i++) a[i] = As[k*128 + ty + i*16];
            #pragma unroll
            for (int j = 0; j < 8; j++) b[j] = Bs[k*128 + tx + j*16];
            #pragma unroll
            for (int i = 0; i < 8; i++)
                #pragma unroll
                for (int j = 0; j < 8; j++) acc[i][j] += a[i]*b[j];
        }
        __syncthreads();
    }
    #pragma unroll
    for (int i = 0; i < 8; i++) {
        int row = rowBase + ty + i*16;
        #pragma unroll
        for (int j = 0; j < 8; j++) {
            int c = colBase + tx + j*16;
            out[(size_t)row*E_ + c] = acc[i][j] + __ldg(bias + c);
        }
    }
}

// ---------------- attention: 1 CTA per (b,h); K,V,Q,S resident in smem ----------------
// smem: Ks[256][65] Vs[256][65] Qs[64][65] Ss[64][257]  = 215552 B
#define KS_PAD 65
#define SS_PAD 257
#define ATTN_SMEM ((256*KS_PAD*2 + 64*KS_PAD + 64*SS_PAD) * 4)

__global__ void attn_kernel() {
    extern __shared__ float sm[];
    float* Ks = sm;                       // [256][65]
    float* Vs = Ks + 256*KS_PAD;          // [256][65]
    float* Qs = Vs + 256*KS_PAD;          // [64][65]
    float* Ss = Qs + 64*KS_PAD;           // [64][257]

    const int bh = blockIdx.x;            // b*H + h
    const int t  = threadIdx.x;
    const int ty = t >> 4, tx = t & 15;
    const int b  = bh >> 3, h = bh & 7;

    const float* kbase = g_k + (size_t)bh * N_ * D_;
    const float* vbase = g_v + (size_t)bh * N_ * D_;
    const float* qbase = g_q + (size_t)bh * N_ * D_;
    const float* bbase = g_bias + (size_t)bh * N_ * N_;

    // load K,V (256x64 each, float4 coalesced)
    for (int f = t; f < 4096; f += 256) {
        int row = f >> 4, c4 = (f & 15) * 4;
        float4 kv = ((const float4*)kbase)[f];
        float* kd = Ks + row*KS_PAD + c4;
        kd[0]=kv.x; kd[1]=kv.y; kd[2]=kv.z; kd[3]=kv.w;
        float4 vv = ((const float4*)vbase)[f];
        float* vd = Vs + row*KS_PAD + c4;
        vd[0]=vv.x; vd[1]=vv.y; vd[2]=vv.z; vd[3]=vv.w;
    }
    __syncthreads();

    for (int q0 = 0; q0 < N_; q0 += 64) {
        // load Q chunk 64x64
        for (int f = t; f < 1024; f += 256) {
            int row = f >> 4, c4 = (f & 15) * 4;
            float4 qv = ((const float4*)(qbase + q0*D_))[f];
            float* qd = Qs + row*KS_PAD + c4;
            qd[0]=qv.x; qd[1]=qv.y; qd[2]=qv.z; qd[3]=qv.w;
        }
        __syncthreads();

        // S[64][256] = Q K^T   (rows: ty+i*16, cols: tx+j*16 — bank-conflict-free)
        {
            float acc[4][16];
            #pragma unroll
            for (int i = 0; i < 4; i++)
                #pragma unroll
                for (int j = 0; j < 16; j++) acc[i][j] = 0.f;
            #pragma unroll 4
            for (int k = 0; k < 64; k++) {
                float a[4], bv[16];
                #pragma unroll
                for (int i = 0; i < 4; i++)  a[i]  = Qs[(ty + i*16)*KS_PAD + k];
                #pragma unroll
                for (int j = 0; j < 16; j++) bv[j] = Ks[(tx + j*16)*KS_PAD + k];
                #pragma unroll
                for (int i = 0; i < 4; i++)
                    #pragma unroll
                    for (int j = 0; j < 16; j++) acc[i][j] += a[i]*bv[j];
            }
            #pragma unroll
            for (int i = 0; i < 4; i++) {
                int r = ty + i*16;
                const float* bp = bbase + (size_t)(q0 + r) * N_;
                #pragma unroll
                for (int j = 0; j < 16; j++) {
                    int c = tx + j*16;
                    Ss[r*SS_PAD + c] = acc[i][j] + __ldg(bp + c);
                }
            }
        }
        __syncthreads();

        // softmax over 256 cols, one warp handles 8 rows
        {
            int warp = t >> 5, lane = t & 31;
            for (int rr = warp; rr < 64; rr += 8) {
                float vals[8];
                float mx = -1e30f;
                #pragma unroll
                for (int kk = 0; kk < 8; kk++) {
                    vals[kk] = Ss[rr*SS_PAD + lane + kk*32];
                    mx = fmaxf(mx, vals[kk]);
                }
                #pragma unroll
                for (int off = 16; off; off >>= 1)
                    mx = fmaxf(mx, __shfl_xor_sync(0xffffffffu, mx, off));
                float s = 0.f;
                #pragma unroll
                for (int kk = 0; kk < 8; kk++) { vals[kk] = __expf(vals[kk]-mx); s += vals[kk]; }
                #pragma unroll
                for (int off = 16; off; off >>= 1)
                    s += __shfl_xor_sync(0xffffffffu, s, off);
                float inv = 1.0f / s;
                #pragma unroll
                for (int kk = 0; kk < 8; kk++)
                    Ss[rr*SS_PAD + lane + kk*32] = vals[kk]*inv;
            }
        }
        __syncthreads();

        // O[64][64] = P V
        {
            float oacc[4][4];
            #pragma unroll
            for (int i = 0; i < 4; i++)
                #pragma unroll
                for (int j = 0; j < 4; j++) oacc[i][j] = 0.f;
            #pragma unroll 4
            for (int m = 0; m < 256; m++) {
                float p[4], vv[4];
                #pragma unroll
                for (int i = 0; i < 4; i++) p[i]  = Ss[(ty + i*16)*SS_PAD + m];
                #pragma unroll
                for (int j = 0; j < 4; j++) vv[j] = Vs[m*KS_PAD + tx + j*16];
                #pragma unroll
                for (int i = 0; i < 4; i++)
                    #pragma unroll
                    for (int j = 0; j < 4; j++) oacc[i][j] += p[i]*vv[j];
            }
            #pragma unroll
            for (int i = 0; i < 4; i++) {
                int r = q0 + ty + i*16;
                float* op = g_o + ((size_t)b*N_ + r)*E_ + h*D_;
                #pragma unroll
                for (int j = 0; j < 4; j++) op[tx + j*16] = oacc[i][j];
            }
        }
        __syncthreads();
    }
}

// ---------------- launcher ----------------
extern "C" void kernel_launch(void* const* d_in, const int* in_sizes, int n_in,
                              void* d_out, int out_size) {
    const float* x     = (const float*)d_in[0];
    const float* U     = (const float*)d_in[1];
    const float* w_qkv = (const float*)d_in[2];
    const float* b_qkv = (const float*)d_in[3];
    const float* w_out = (const float*)d_in[4];
    const float* b_out = (const float*)d_in[5];
    const float* w_u   = (const float*)d_in[6];
    const float* b_u   = (const float*)d_in[7];
    float* out = (float*)d_out;

    // bias tensor [B,H,N,N]
    bias_kernel<<<(B_*N_*N_ + 255)/256, 256>>>(U, w_u, b_u);

    // QKV projection: [8192,1536] = x @ w_qkv^T
    { dim3 g(1536/128, (B_*N_)/128); qkv_gemm<<<g, 256>>>(x, w_qkv, b_qkv); }

    // attention per (b,h)
    cudaFuncSetAttribute(attn_kernel, cudaFuncAttributeMaxDynamicSharedMemorySize, ATTN_SMEM);
    attn_kernel<<<B_*H_, 256, ATTN_SMEM>>>();

    // output projection: [8192,512] = o @ w_out^T
    { dim3 g(512/128, (B_*N_)/128); out_gemm<<<g, 256>>>(w_out, b_out, out); }
}

// round 5
// speedup vs baseline: 1.7350x; 1.7350x over previous
#include <cuda_runtime.h>
#include <cuda_bf16.h>
#include <cstdint>
#include <math.h>

#define B_   32
#define N_   256
#define E_   512
#define H_   8
#define D_   64
#define ID_  8
#define KDIM 512

// ---------------- device-global scratch (alloc-free) ----------------
__device__ float g_q[(size_t)B_*H_*N_*D_];      // 16 MB (pre-scaled by D^-0.5)
__device__ float g_k[(size_t)B_*H_*N_*D_];      // 16 MB
__device__ float g_v[(size_t)B_*H_*N_*D_];      // 16 MB
__device__ float g_bias[(size_t)B_*H_*N_*N_];   // 64 MB
__device__ float g_o[(size_t)B_*N_*E_];         // 16 MB

// ================= helpers =================
__device__ __forceinline__ uint32_t smem_u32(const void* p) {
    uint32_t a;
    asm("{ .reg .u64 t; cvta.to.shared.u64 t, %1; cvt.u32.u64 %0, t; }" : "=r"(a) : "l"(p));
    return a;
}
__device__ __forceinline__ void ldsm4(uint32_t* r, uint32_t addr) {
    asm volatile("ldmatrix.sync.aligned.m8n8.x4.shared.b16 {%0,%1,%2,%3}, [%4];"
        : "=r"(r[0]), "=r"(r[1]), "=r"(r[2]), "=r"(r[3]) : "r"(addr));
}
__device__ __forceinline__ void mma16816(float* c, const uint32_t* a, const uint32_t* b) {
    asm volatile("mma.sync.aligned.m16n8k16.row.col.f32.bf16.bf16.f32 "
        "{%0,%1,%2,%3}, {%4,%5,%6,%7}, {%8,%9}, {%0,%1,%2,%3};"
        : "+f"(c[0]), "+f"(c[1]), "+f"(c[2]), "+f"(c[3])
        : "r"(a[0]), "r"(a[1]), "r"(a[2]), "r"(a[3]), "r"(b[0]), "r"(b[1]));
}
__device__ __forceinline__ void split2(float x, float y,
                                       __nv_bfloat162& hi, __nv_bfloat162& lo) {
    __nv_bfloat16 hx = __float2bfloat16(x), hy = __float2bfloat16(y);
    hi.x = hx; hi.y = hy;
    lo.x = __float2bfloat16(x - __bfloat162float(hx));
    lo.y = __float2bfloat16(y - __bfloat162float(hy));
}

// ---------------- bias = U @ w_u^T + b_u, transposed to [B,H,N,N] ----------------
__global__ void bias_kernel(const float* __restrict__ U,
                            const float* __restrict__ w_u,
                            const float* __restrict__ b_u) {
    __shared__ float sw[H_*ID_];
    __shared__ float sb[H_];
    if (threadIdx.x < H_*ID_) sw[threadIdx.x] = w_u[threadIdx.x];
    if (threadIdx.x < H_)     sb[threadIdx.x] = b_u[threadIdx.x];
    __syncthreads();
    int idx = blockIdx.x * blockDim.x + threadIdx.x;
    if (idx >= B_*N_*N_) return;
    const float4* up = (const float4*)(U + (size_t)idx * ID_);
    float4 u0 = up[0], u1 = up[1];
    float u[8] = {u0.x,u0.y,u0.z,u0.w,u1.x,u1.y,u1.z,u1.w};
    int b  = idx / (N_*N_);
    int nm = idx - b * (N_*N_);
    #pragma unroll
    for (int h = 0; h < H_; h++) {
        float s = sb[h];
        #pragma unroll
        for (int i = 0; i < 8; i++) s += u[i] * sw[h*ID_ + i];
        g_bias[((size_t)(b*H_ + h)) * (N_*N_) + nm] = s;
    }
}

// ============ HMMA GEMM: C[M,NC] = A[M,512] * W[NC,512]^T, bf16 hi/lo split ============
// CTA tile 128x128, k-step 32, 8 warps (2x4) of 64x32 warp tiles, double buffered.
#define TK 32
#define NKS (KDIM/TK)        // 16
#define LDS_BF 40            // bf16 row stride (80 bytes: 16B aligned, conflict-free ldmatrix)
#define MAT_B (128*LDS_BF*2) // 10240 bytes per matrix tile
#define STG_B (4*MAT_B)      // Ahi,Alo,Whi,Wlo = 40960
#define GEMM_SMEM (2*STG_B)  // 81920

__global__ __launch_bounds__(256)
void gemm_mma(const float* __restrict__ Ain, const float* __restrict__ W,
              const float* __restrict__ bias, int mode, float* __restrict__ out) {
    extern __shared__ char dsm[];
    const int t    = threadIdx.x;
    const int lane = t & 31;
    const int wid  = t >> 5;
    const int warpM = wid >> 2;          // 0..1
    const int warpN = wid & 3;           // 0..3
    const int rowBase = blockIdx.y * 128;
    const int colBase = blockIdx.x * 128;
    // CRITICAL: device symbols must be resolved in device code, not passed from host
    const float* A = (mode == 1) ? (const float*)g_o : Ain;
    const float* Abase = A + (size_t)rowBase * KDIM;
    const float* Wbase = W + (size_t)colBase * KDIM;
    const uint32_t smb = smem_u32(dsm);

    float acc[4][4][4];
    #pragma unroll
    for (int i = 0; i < 4; i++)
        #pragma unroll
        for (int j = 0; j < 4; j++)
            #pragma unroll
            for (int e = 0; e < 4; e++) acc[i][j][e] = 0.f;

    float4 ar[4], wr[4];

    // global load of k-slab ks into regs
    auto ldreg = [&](int ks) {
        int k0 = ks * TK;
        #pragma unroll
        for (int l = 0; l < 4; l++) {
            int f = t + l*256;           // 0..1023
            int row = f >> 3, c4 = f & 7;
            ar[l] = *(const float4*)(Abase + (size_t)row*KDIM + k0 + c4*4);
            wr[l] = *(const float4*)(Wbase + (size_t)row*KDIM + k0 + c4*4);
        }
    };
    // convert + store regs into smem stage s
    auto streg = [&](int s) {
        char* base = dsm + s*STG_B;
        #pragma unroll
        for (int l = 0; l < 4; l++) {
            int f = t + l*256;
            int row = f >> 3, c4 = f & 7;
            int off = row*(LDS_BF*2) + c4*8;        // 4 bf16 = 8 bytes per float4
            __nv_bfloat162 h0, l0, h1, l1;
            split2(ar[l].x, ar[l].y, h0, l0);
            split2(ar[l].z, ar[l].w, h1, l1);
            *(__nv_bfloat162*)(base + off)            = h0;
            *(__nv_bfloat162*)(base + off + 4)        = h1;
            *(__nv_bfloat162*)(base + MAT_B + off)    = l0;
            *(__nv_bfloat162*)(base + MAT_B + off + 4)= l1;
            split2(wr[l].x, wr[l].y, h0, l0);
            split2(wr[l].z, wr[l].w, h1, l1);
            *(__nv_bfloat162*)(base + 2*MAT_B + off)     = h0;
            *(__nv_bfloat162*)(base + 2*MAT_B + off + 4) = h1;
            *(__nv_bfloat162*)(base + 3*MAT_B + off)     = l0;
            *(__nv_bfloat162*)(base + 3*MAT_B + off + 4) = l1;
        }
    };

    ldreg(0);
    streg(0);
    __syncthreads();

    for (int ks = 0; ks < NKS; ks++) {
        int s = ks & 1;
        if (ks + 1 < NKS) ldreg(ks + 1);

        uint32_t stg = smb + s*STG_B;
        #pragma unroll
        for (int k16 = 0; k16 < 2; k16++) {
            int colb = k16 * 16;
            // W fragments: 4 n-tiles via 2 ldmatrix.x4 each for hi and lo
            uint32_t whi[4][2], wlo[4][2];
            {
                int l8  = lane & 7, sel = lane >> 3;
                #pragma unroll
                for (int np = 0; np < 2; np++) {
                    int wrow = warpN*32 + np*16 + (sel >> 1)*8 + l8;
                    int wcol = colb + (sel & 1)*8;
                    uint32_t off = (uint32_t)(wrow*(LDS_BF*2) + wcol*2);
                    uint32_t r[4];
                    ldsm4(r, stg + 2*MAT_B + off);
                    whi[np*2+0][0]=r[0]; whi[np*2+0][1]=r[1];
                    whi[np*2+1][0]=r[2]; whi[np*2+1][1]=r[3];
                    ldsm4(r, stg + 3*MAT_B + off);
                    wlo[np*2+0][0]=r[0]; wlo[np*2+0][1]=r[1];
                    wlo[np*2+1][0]=r[2]; wlo[np*2+1][1]=r[3];
                }
            }
            // A fragments per m-tile; 3-term split
            int r8 = lane & 7, half = (lane >> 3) & 1, kk = lane >> 4;
            #pragma unroll
            for (int mi = 0; mi < 4; mi++) {
                int arow = warpM*64 + mi*16 + half*8 + r8;
                int acol = colb + kk*8;
                uint32_t off = (uint32_t)(arow*(LDS_BF*2) + acol*2);
                uint32_t a[4];
                ldsm4(a, stg + off);                 // Ahi
                #pragma unroll
                for (int ni = 0; ni < 4; ni++) mma16816(acc[mi][ni], a, whi[ni]);
                #pragma unroll
                for (int ni = 0; ni < 4; ni++) mma16816(acc[mi][ni], a, wlo[ni]);
                ldsm4(a, stg + MAT_B + off);         // Alo
                #pragma unroll
                for (int ni = 0; ni < 4; ni++) mma16816(acc[mi][ni], a, whi[ni]);
            }
        }
        __syncthreads();
        if (ks + 1 < NKS) {
            streg(s ^ 1);
            __syncthreads();
        }
    }

    // epilogue
    const int gID = lane >> 2, tg = lane & 3;
    #pragma unroll
    for (int mi = 0; mi < 4; mi++) {
        #pragma unroll
        for (int ni = 0; ni < 4; ni++) {
            #pragma unroll
            for (int e = 0; e < 4; e++) {
                int r = rowBase + warpM*64 + mi*16 + gID + (e >> 1)*8;
                int c = colBase + warpN*32 + ni*8 + tg*2 + (e & 1);
                float val = acc[mi][ni][e] + __ldg(bias + c);
                if (mode == 0) {
                    int bb = r >> 8, n = r & 255;
                    int sec = c >> 9;
                    int jj  = c & 511;
                    int h = jj >> 6, d = jj & 63;
                    size_t dst = ((size_t)((bb*H_ + h)*N_ + n))*D_ + d;
                    if      (sec == 0) g_q[dst] = val * 0.125f;
                    else if (sec == 1) g_k[dst] = val;
                    else               g_v[dst] = val;
                } else {
                    out[(size_t)r*E_ + c] = val;
                }
            }
        }
    }
}

// ---------------- attention: 1 CTA per (b,h,qchunk); vectorized smem streams ----------------
#define KS_PAD 68
#define VT_PAD 260
#define SS_PAD 260
#define ATTN_SMEM ((256*KS_PAD + 64*VT_PAD + 64*KS_PAD + 64*SS_PAD) * 4)

__global__ void attn_kernel() {
    extern __shared__ float sm[];
    float* Ks = sm;                         // [256][68]  (seq x d)
    float* Vt = Ks + 256*KS_PAD;            // [64][260]  (d x seq, transposed)
    float* Qs = Vt + 64*VT_PAD;             // [64][68]
    float* Ss = Qs + 64*KS_PAD;             // [64][260]

    const int bh = blockIdx.x;              // b*H + h
    const int q0 = blockIdx.y << 6;
    const int t  = threadIdx.x;
    const int ty = t >> 4, tx = t & 15;
    const int b  = bh >> 3, h = bh & 7;

    const float* kbase = g_k + (size_t)bh * N_ * D_;
    const float* vbase = g_v + (size_t)bh * N_ * D_;
    const float* qbase = g_q + (size_t)bh * N_ * D_;
    const float* bbase = g_bias + (size_t)bh * N_ * N_;

    for (int f = t; f < 4096; f += 256) {
        int row = f >> 4, c4 = (f & 15) * 4;
        float4 kv = ((const float4*)kbase)[f];
        float* kd = Ks + row*KS_PAD + c4;
        kd[0]=kv.x; kd[1]=kv.y; kd[2]=kv.z; kd[3]=kv.w;
        float4 vv = ((const float4*)vbase)[f];
        Vt[(c4+0)*VT_PAD + row] = vv.x;
        Vt[(c4+1)*VT_PAD + row] = vv.y;
        Vt[(c4+2)*VT_PAD + row] = vv.z;
        Vt[(c4+3)*VT_PAD + row] = vv.w;
    }
    for (int f = t; f < 1024; f += 256) {
        int row = f >> 4, c4 = (f & 15) * 4;
        float4 qv = ((const float4*)(qbase + q0*D_))[f];
        float* qd = Qs + row*KS_PAD + c4;
        qd[0]=qv.x; qd[1]=qv.y; qd[2]=qv.z; qd[3]=qv.w;
    }
    __syncthreads();

    // S[64][256] = Q K^T, float4 along k
    {
        float acc[4][16];
        #pragma unroll
        for (int i = 0; i < 4; i++)
            #pragma unroll
            for (int j = 0; j < 16; j++) acc[i][j] = 0.f;
        for (int k0 = 0; k0 < 64; k0 += 4) {
            float4 a4[4], b4[16];
            #pragma unroll
            for (int i = 0; i < 4; i++)  a4[i] = *(const float4*)&Qs[(ty + i*16)*KS_PAD + k0];
            #pragma unroll
            for (int j = 0; j < 16; j++) b4[j] = *(const float4*)&Ks[(tx + j*16)*KS_PAD + k0];
            #pragma unroll
            for (int i = 0; i < 4; i++)
                #pragma unroll
                for (int j = 0; j < 16; j++) {
                    acc[i][j] += a4[i].x*b4[j].x + a4[i].y*b4[j].y
                               + a4[i].z*b4[j].z + a4[i].w*b4[j].w;
                }
        }
        #pragma unroll
        for (int i = 0; i < 4; i++) {
            int r = ty + i*16;
            const float* bp = bbase + (size_t)(q0 + r) * N_;
            #pragma unroll
            for (int j = 0; j < 16; j++) {
                int c = tx + j*16;
                Ss[r*SS_PAD + c] = acc[i][j] + __ldg(bp + c);
            }
        }
    }
    __syncthreads();

    // softmax: one warp per 8 rows
    {
        int warp = t >> 5, lane = t & 31;
        for (int rr = warp; rr < 64; rr += 8) {
            float vals[8];
            float mx = -1e30f;
            #pragma unroll
            for (int kk = 0; kk < 8; kk++) {
                vals[kk] = Ss[rr*SS_PAD + lane + kk*32];
                mx = fmaxf(mx, vals[kk]);
            }
            #pragma unroll
            for (int off = 16; off; off >>= 1)
                mx = fmaxf(mx, __shfl_xor_sync(0xffffffffu, mx, off));
            float s = 0.f;
            #pragma unroll
            for (int kk = 0; kk < 8; kk++) { vals[kk] = __expf(vals[kk]-mx); s += vals[kk]; }
            #pragma unroll
            for (int off = 16; off; off >>= 1)
                s += __shfl_xor_sync(0xffffffffu, s, off);
            float inv = 1.0f / s;
            #pragma unroll
            for (int kk = 0; kk < 8; kk++)
                Ss[rr*SS_PAD + lane + kk*32] = vals[kk]*inv;
        }
    }
    __syncthreads();

    // O[64][64] = P V, float4 along m via Vt
    {
        float oacc[4][4];
        #pragma unroll
        for (int i = 0; i < 4; i++)
            #pragma unroll
            for (int j = 0; j < 4; j++) oacc[i][j] = 0.f;
        for (int m0 = 0; m0 < 256; m0 += 4) {
            float4 p4[4], v4[4];
            #pragma unroll
            for (int i = 0; i < 4; i++) p4[i] = *(const float4*)&Ss[(ty + i*16)*SS_PAD + m0];
            #pragma unroll
            for (int j = 0; j < 4; j++) v4[j] = *(const float4*)&Vt[(tx + j*16)*VT_PAD + m0];
            #pragma unroll
            for (int i = 0; i < 4; i++)
                #pragma unroll
                for (int j = 0; j < 4; j++) {
                    oacc[i][j] += p4[i].x*v4[j].x + p4[i].y*v4[j].y
                                + p4[i].z*v4[j].z + p4[i].w*v4[j].w;
                }
        }
        #pragma unroll
        for (int i = 0; i < 4; i++) {
            int r = q0 + ty + i*16;
            float* op = g_o + ((size_t)b*N_ + r)*E_ + h*D_;
            #pragma unroll
            for (int j = 0; j < 4; j++) op[tx + j*16] = oacc[i][j];
        }
    }
}

// ---------------- launcher ----------------
extern "C" void kernel_launch(void* const* d_in, const int* in_sizes, int n_in,
                              void* d_out, int out_size) {
    const float* x     = (const float*)d_in[0];
    const float* U     = (const float*)d_in[1];
    const float* w_qkv = (const float*)d_in[2];
    const float* b_qkv = (const float*)d_in[3];
    const float* w_out = (const float*)d_in[4];
    const float* b_out = (const float*)d_in[5];
    const float* w_u   = (const float*)d_in[6];
    const float* b_u   = (const float*)d_in[7];
    float* out = (float*)d_out;

    cudaFuncSetAttribute(gemm_mma, cudaFuncAttributeMaxDynamicSharedMemorySize, GEMM_SMEM);
    cudaFuncSetAttribute(attn_kernel, cudaFuncAttributeMaxDynamicSharedMemorySize, ATTN_SMEM);

    // bias tensor [B,H,N,N]
    bias_kernel<<<(B_*N_*N_ + 255)/256, 256>>>(U, w_u, b_u);

    // QKV projection (tensor cores): [8192,1536] = x @ w_qkv^T
    { dim3 g(1536/128, (B_*N_)/128); gemm_mma<<<g, 256, GEMM_SMEM>>>(x, w_qkv, b_qkv, 0, nullptr); }

    // attention per (b,h,q-chunk)
    { dim3 g(B_*H_, N_/64); attn_kernel<<<g, 256, ATTN_SMEM>>>(); }

    // output projection (tensor cores): A resolved to g_o inside the kernel (mode=1)
    { dim3 g(512/128, (B_*N_)/128); gemm_mma<<<g, 256, GEMM_SMEM>>>(nullptr, w_out, b_out, 1, out); }
}

// round 6
// speedup vs baseline: 2.2546x; 1.2995x over previous
#include <cuda_runtime.h>
#include <cuda_bf16.h>
#include <cstdint>
#include <math.h>

#define B_   32
#define N_   256
#define E_   512
#define H_   8
#define D_   64
#define ID_  8
#define KDIM 512

// ---------------- device-global scratch (alloc-free) ----------------
__device__ float g_q[(size_t)B_*H_*N_*D_];      // pre-scaled by D^-0.5
__device__ float g_k[(size_t)B_*H_*N_*D_];
__device__ float g_v[(size_t)B_*H_*N_*D_];
__device__ float g_bias[(size_t)B_*H_*N_*N_];
__device__ float g_o[(size_t)B_*N_*E_];

// ================= helpers =================
__device__ __forceinline__ uint32_t smem_u32(const void* p) {
    uint32_t a;
    asm("{ .reg .u64 t; cvta.to.shared.u64 t, %1; cvt.u32.u64 %0, t; }" : "=r"(a) : "l"(p));
    return a;
}
__device__ __forceinline__ void ldsm4(uint32_t* r, uint32_t addr) {
    asm volatile("ldmatrix.sync.aligned.m8n8.x4.shared.b16 {%0,%1,%2,%3}, [%4];"
        : "=r"(r[0]), "=r"(r[1]), "=r"(r[2]), "=r"(r[3]) : "r"(addr));
}
__device__ __forceinline__ void ldsm4t(uint32_t* r, uint32_t addr) {
    asm volatile("ldmatrix.sync.aligned.m8n8.x4.trans.shared.b16 {%0,%1,%2,%3}, [%4];"
        : "=r"(r[0]), "=r"(r[1]), "=r"(r[2]), "=r"(r[3]) : "r"(addr));
}
__device__ __forceinline__ void mma16816(float* c, const uint32_t* a, const uint32_t* b) {
    asm volatile("mma.sync.aligned.m16n8k16.row.col.f32.bf16.bf16.f32 "
        "{%0,%1,%2,%3}, {%4,%5,%6,%7}, {%8,%9}, {%0,%1,%2,%3};"
        : "+f"(c[0]), "+f"(c[1]), "+f"(c[2]), "+f"(c[3])
        : "r"(a[0]), "r"(a[1]), "r"(a[2]), "r"(a[3]), "r"(b[0]), "r"(b[1]));
}
__device__ __forceinline__ void split2(float x, float y,
                                       __nv_bfloat162& hi, __nv_bfloat162& lo) {
    __nv_bfloat16 hx = __float2bfloat16(x), hy = __float2bfloat16(y);
    hi.x = hx; hi.y = hy;
    lo.x = __float2bfloat16(x - __bfloat162float(hx));
    lo.y = __float2bfloat16(y - __bfloat162float(hy));
}
__device__ __forceinline__ void pksplit(float x, float y, uint32_t& hi, uint32_t& lo) {
    __nv_bfloat162 H, L;
    split2(x, y, H, L);
    hi = *reinterpret_cast<uint32_t*>(&H);
    lo = *reinterpret_cast<uint32_t*>(&L);
}

// ---------------- bias = U @ w_u^T + b_u, transposed to [B,H,N,N] ----------------
__global__ void bias_kernel(const float* __restrict__ U,
                            const float* __restrict__ w_u,
                            const float* __restrict__ b_u) {
    __shared__ float sw[H_*ID_];
    __shared__ float sb[H_];
    if (threadIdx.x < H_*ID_) sw[threadIdx.x] = w_u[threadIdx.x];
    if (threadIdx.x < H_)     sb[threadIdx.x] = b_u[threadIdx.x];
    __syncthreads();
    int idx = blockIdx.x * blockDim.x + threadIdx.x;
    if (idx >= B_*N_*N_) return;
    const float4* up = (const float4*)(U + (size_t)idx * ID_);
    float4 u0 = up[0], u1 = up[1];
    float u[8] = {u0.x,u0.y,u0.z,u0.w,u1.x,u1.y,u1.z,u1.w};
    int b  = idx / (N_*N_);
    int nm = idx - b * (N_*N_);
    #pragma unroll
    for (int h = 0; h < H_; h++) {
        float s = sb[h];
        #pragma unroll
        for (int i = 0; i < 8; i++) s += u[i] * sw[h*ID_ + i];
        g_bias[((size_t)(b*H_ + h)) * (N_*N_) + nm] = s;
    }
}

// ============ HMMA GEMM (same as R5, + min-blocks 2) ============
#define TK 32
#define NKS (KDIM/TK)
#define LDS_BF 40
#define MAT_B (128*LDS_BF*2)
#define STG_B (4*MAT_B)
#define GEMM_SMEM (2*STG_B)

__global__ __launch_bounds__(256, 2)
void gemm_mma(const float* __restrict__ Ain, const float* __restrict__ W,
              const float* __restrict__ bias, int mode, float* __restrict__ out) {
    extern __shared__ char dsm[];
    const int t    = threadIdx.x;
    const int lane = t & 31;
    const int wid  = t >> 5;
    const int warpM = wid >> 2;
    const int warpN = wid & 3;
    const int rowBase = blockIdx.y * 128;
    const int colBase = blockIdx.x * 128;
    const float* A = (mode == 1) ? (const float*)g_o : Ain;
    const float* Abase = A + (size_t)rowBase * KDIM;
    const float* Wbase = W + (size_t)colBase * KDIM;
    const uint32_t smb = smem_u32(dsm);

    float acc[4][4][4];
    #pragma unroll
    for (int i = 0; i < 4; i++)
        #pragma unroll
        for (int j = 0; j < 4; j++)
            #pragma unroll
            for (int e = 0; e < 4; e++) acc[i][j][e] = 0.f;

    float4 ar[4], wr[4];

    auto ldreg = [&](int ks) {
        int k0 = ks * TK;
        #pragma unroll
        for (int l = 0; l < 4; l++) {
            int f = t + l*256;
            int row = f >> 3, c4 = f & 7;
            ar[l] = *(const float4*)(Abase + (size_t)row*KDIM + k0 + c4*4);
            wr[l] = *(const float4*)(Wbase + (size_t)row*KDIM + k0 + c4*4);
        }
    };
    auto streg = [&](int s) {
        char* base = dsm + s*STG_B;
        #pragma unroll
        for (int l = 0; l < 4; l++) {
            int f = t + l*256;
            int row = f >> 3, c4 = f & 7;
            int off = row*(LDS_BF*2) + c4*8;
            __nv_bfloat162 h0, l0, h1, l1;
            split2(ar[l].x, ar[l].y, h0, l0);
            split2(ar[l].z, ar[l].w, h1, l1);
            *(__nv_bfloat162*)(base + off)            = h0;
            *(__nv_bfloat162*)(base + off + 4)        = h1;
            *(__nv_bfloat162*)(base + MAT_B + off)    = l0;
            *(__nv_bfloat162*)(base + MAT_B + off + 4)= l1;
            split2(wr[l].x, wr[l].y, h0, l0);
            split2(wr[l].z, wr[l].w, h1, l1);
            *(__nv_bfloat162*)(base + 2*MAT_B + off)     = h0;
            *(__nv_bfloat162*)(base + 2*MAT_B + off + 4) = h1;
            *(__nv_bfloat162*)(base + 3*MAT_B + off)     = l0;
            *(__nv_bfloat162*)(base + 3*MAT_B + off + 4) = l1;
        }
    };

    ldreg(0);
    streg(0);
    __syncthreads();

    for (int ks = 0; ks < NKS; ks++) {
        int s = ks & 1;
        if (ks + 1 < NKS) ldreg(ks + 1);

        uint32_t stg = smb + s*STG_B;
        #pragma unroll
        for (int k16 = 0; k16 < 2; k16++) {
            int colb = k16 * 16;
            uint32_t whi[4][2], wlo[4][2];
            {
                int l8  = lane & 7, sel = lane >> 3;
                #pragma unroll
                for (int np = 0; np < 2; np++) {
                    int wrow = warpN*32 + np*16 + (sel >> 1)*8 + l8;
                    int wcol = colb + (sel & 1)*8;
                    uint32_t off = (uint32_t)(wrow*(LDS_BF*2) + wcol*2);
                    uint32_t r[4];
                    ldsm4(r, stg + 2*MAT_B + off);
                    whi[np*2+0][0]=r[0]; whi[np*2+0][1]=r[1];
                    whi[np*2+1][0]=r[2]; whi[np*2+1][1]=r[3];
                    ldsm4(r, stg + 3*MAT_B + off);
                    wlo[np*2+0][0]=r[0]; wlo[np*2+0][1]=r[1];
                    wlo[np*2+1][0]=r[2]; wlo[np*2+1][1]=r[3];
                }
            }
            int r8 = lane & 7, half = (lane >> 3) & 1, kk = lane >> 4;
            #pragma unroll
            for (int mi = 0; mi < 4; mi++) {
                int arow = warpM*64 + mi*16 + half*8 + r8;
                int acol = colb + kk*8;
                uint32_t off = (uint32_t)(arow*(LDS_BF*2) + acol*2);
                uint32_t a[4];
                ldsm4(a, stg + off);
                #pragma unroll
                for (int ni = 0; ni < 4; ni++) mma16816(acc[mi][ni], a, whi[ni]);
                #pragma unroll
                for (int ni = 0; ni < 4; ni++) mma16816(acc[mi][ni], a, wlo[ni]);
                ldsm4(a, stg + MAT_B + off);
                #pragma unroll
                for (int ni = 0; ni < 4; ni++) mma16816(acc[mi][ni], a, whi[ni]);
            }
        }
        __syncthreads();
        if (ks + 1 < NKS) {
            streg(s ^ 1);
            __syncthreads();
        }
    }

    const int gID = lane >> 2, tg = lane & 3;
    #pragma unroll
    for (int mi = 0; mi < 4; mi++) {
        #pragma unroll
        for (int ni = 0; ni < 4; ni++) {
            #pragma unroll
            for (int e = 0; e < 4; e++) {
                int r = rowBase + warpM*64 + mi*16 + gID + (e >> 1)*8;
                int c = colBase + warpN*32 + ni*8 + tg*2 + (e & 1);
                float val = acc[mi][ni][e] + __ldg(bias + c);
                if (mode == 0) {
                    int bb = r >> 8, n = r & 255;
                    int sec = c >> 9;
                    int jj  = c & 511;
                    int h = jj >> 6, d = jj & 63;
                    size_t dst = ((size_t)((bb*H_ + h)*N_ + n))*D_ + d;
                    if      (sec == 0) g_q[dst] = val * 0.125f;
                    else if (sec == 1) g_k[dst] = val;
                    else               g_v[dst] = val;
                } else {
                    out[(size_t)r*E_ + c] = val;
                }
            }
        }
    }
}

// ======== attention: HMMA, register-resident softmax, 1 CTA per (b,h,q0) ========
// smem bf16 tiles (stride 72 halfwords = 144B: ldmatrix conflict-free):
//   KHI [256][72], KLO, QHI [64][72], QLO, VHI [256][72], VLO (row-major [m][d])
// O partial region (fp32, 8 warps x 32x64) ALIASES the dead K region after S-phase.
#define KP 72
#define AT_KHI 0
#define AT_KLO 36864
#define AT_QHI 73728
#define AT_QLO 82944
#define AT_VHI 92160
#define AT_VLO 129024
#define AT_OP  0
#define ATTN_SMEM 165888

__global__ __launch_bounds__(256)
void attn_kernel() {
    extern __shared__ char asm_[];
    __shared__ float s_red[4][64];
    __shared__ float s_inv[64];

    const int bh = blockIdx.x;
    const int q0 = blockIdx.y << 6;
    const int t  = threadIdx.x;
    const int lane = t & 31;
    const int wid  = t >> 5;
    const int warpM = wid >> 2;      // 0..1 -> 32 q-rows each
    const int warpN = wid & 3;       // 0..3 -> 64-key slice each
    const int gID = lane >> 2, tg = lane & 3;
    const int b  = bh >> 3, h = bh & 7;
    const uint32_t smb = smem_u32(asm_);

    const float* kbase = g_k + (size_t)bh * N_ * D_;
    const float* vbase = g_v + (size_t)bh * N_ * D_;
    const float* qbase = g_q + (size_t)bh * N_ * D_ + (size_t)q0 * D_;
    const float* bbase = g_bias + (size_t)bh * N_ * N_;

    // ---- load K,V (256x64) and Q (64x64), fp32 -> bf16 hi/lo smem ----
    for (int f = t; f < 4096; f += 256) {
        int row = f >> 4, c4 = (f & 15) * 4;
        int off = (row*KP + c4) * 2;
        float4 kv = ((const float4*)kbase)[f];
        __nv_bfloat162 h0, l0, h1, l1;
        split2(kv.x, kv.y, h0, l0); split2(kv.z, kv.w, h1, l1);
        *(__nv_bfloat162*)(asm_ + AT_KHI + off)     = h0;
        *(__nv_bfloat162*)(asm_ + AT_KHI + off + 4) = h1;
        *(__nv_bfloat162*)(asm_ + AT_KLO + off)     = l0;
        *(__nv_bfloat162*)(asm_ + AT_KLO + off + 4) = l1;
        float4 vv = ((const float4*)vbase)[f];
        split2(vv.x, vv.y, h0, l0); split2(vv.z, vv.w, h1, l1);
        *(__nv_bfloat162*)(asm_ + AT_VHI + off)     = h0;
        *(__nv_bfloat162*)(asm_ + AT_VHI + off + 4) = h1;
        *(__nv_bfloat162*)(asm_ + AT_VLO + off)     = l0;
        *(__nv_bfloat162*)(asm_ + AT_VLO + off + 4) = l1;
    }
    for (int f = t; f < 1024; f += 256) {
        int row = f >> 4, c4 = (f & 15) * 4;
        int off = (row*KP + c4) * 2;
        float4 qv = ((const float4*)qbase)[f];
        __nv_bfloat162 h0, l0, h1, l1;
        split2(qv.x, qv.y, h0, l0); split2(qv.z, qv.w, h1, l1);
        *(__nv_bfloat162*)(asm_ + AT_QHI + off)     = h0;
        *(__nv_bfloat162*)(asm_ + AT_QHI + off + 4) = h1;
        *(__nv_bfloat162*)(asm_ + AT_QLO + off)     = l0;
        *(__nv_bfloat162*)(asm_ + AT_QLO + off + 4) = l1;
    }
    __syncthreads();

    // ---- S = Q K^T (warp tile 32 rows x 64 keys), 3-term bf16 split ----
    float acc[2][8][4];
    #pragma unroll
    for (int i = 0; i < 2; i++)
        #pragma unroll
        for (int j = 0; j < 8; j++)
            #pragma unroll
            for (int e = 0; e < 4; e++) acc[i][j][e] = 0.f;

    {
        const int l8 = lane & 7, sel = lane >> 3;
        const int r8 = lane & 7, halfq = (lane >> 3) & 1, k8 = lane >> 4;
        #pragma unroll
        for (int kk = 0; kk < 4; kk++) {
            uint32_t bhi[8][2], blo[8][2];
            #pragma unroll
            for (int np = 0; np < 4; np++) {
                int wrow = warpN*64 + np*16 + (sel >> 1)*8 + l8;
                int wcol = kk*16 + (sel & 1)*8;
                uint32_t off = (uint32_t)((wrow*KP + wcol)*2);
                uint32_t r[4];
                ldsm4(r, smb + AT_KHI + off);
                bhi[np*2+0][0]=r[0]; bhi[np*2+0][1]=r[1];
                bhi[np*2+1][0]=r[2]; bhi[np*2+1][1]=r[3];
                ldsm4(r, smb + AT_KLO + off);
                blo[np*2+0][0]=r[0]; blo[np*2+0][1]=r[1];
                blo[np*2+1][0]=r[2]; blo[np*2+1][1]=r[3];
            }
            #pragma unroll
            for (int mi = 0; mi < 2; mi++) {
                int arow = warpM*32 + mi*16 + halfq*8 + r8;
                int acol = kk*16 + k8*8;
                uint32_t off = (uint32_t)((arow*KP + acol)*2);
                uint32_t a[4];
                ldsm4(a, smb + AT_QHI + off);
                #pragma unroll
                for (int nj = 0; nj < 8; nj++) mma16816(acc[mi][nj], a, bhi[nj]);
                #pragma unroll
                for (int nj = 0; nj < 8; nj++) mma16816(acc[mi][nj], a, blo[nj]);
                ldsm4(a, smb + AT_QLO + off);
                #pragma unroll
                for (int nj = 0; nj < 8; nj++) mma16816(acc[mi][nj], a, bhi[nj]);
            }
        }
    }

    // ---- add bias from gmem ----
    #pragma unroll
    for (int mi = 0; mi < 2; mi++) {
        int r0 = q0 + warpM*32 + mi*16 + gID;
        #pragma unroll
        for (int nj = 0; nj < 8; nj++) {
            int c = warpN*64 + nj*8 + tg*2;
            float2 b0 = *(const float2*)(bbase + (size_t)r0*N_ + c);
            float2 b1 = *(const float2*)(bbase + (size_t)(r0+8)*N_ + c);
            acc[mi][nj][0] += b0.x; acc[mi][nj][1] += b0.y;
            acc[mi][nj][2] += b1.x; acc[mi][nj][3] += b1.y;
        }
    }

    // ---- softmax on fragments (rows distributed as warpM*32+mi*16+gID+h2*8) ----
    // partial max per warp's 64-key slice
    #pragma unroll
    for (int mi = 0; mi < 2; mi++)
        #pragma unroll
        for (int h2 = 0; h2 < 2; h2++) {
            float m = -1e30f;
            #pragma unroll
            for (int nj = 0; nj < 8; nj++) {
                m = fmaxf(m, acc[mi][nj][h2*2+0]);
                m = fmaxf(m, acc[mi][nj][h2*2+1]);
            }
            m = fmaxf(m, __shfl_xor_sync(0xffffffffu, m, 1));
            m = fmaxf(m, __shfl_xor_sync(0xffffffffu, m, 2));
            if (tg == 0) s_red[warpN][warpM*32 + mi*16 + gID + h2*8] = m;
        }
    __syncthreads();
    // final max, exp, partial sum
    float psum[2][2];
    #pragma unroll
    for (int mi = 0; mi < 2; mi++)
        #pragma unroll
        for (int h2 = 0; h2 < 2; h2++) {
            int row = warpM*32 + mi*16 + gID + h2*8;
            float fm = fmaxf(fmaxf(s_red[0][row], s_red[1][row]),
                             fmaxf(s_red[2][row], s_red[3][row]));
            float s = 0.f;
            #pragma unroll
            for (int nj = 0; nj < 8; nj++) {
                float p0 = __expf(acc[mi][nj][h2*2+0] - fm);
                float p1 = __expf(acc[mi][nj][h2*2+1] - fm);
                acc[mi][nj][h2*2+0] = p0; acc[mi][nj][h2*2+1] = p1;
                s += p0 + p1;
            }
            s += __shfl_xor_sync(0xffffffffu, s, 1);
            s += __shfl_xor_sync(0xffffffffu, s, 2);
            psum[mi][h2] = s;
        }
    __syncthreads();   // everyone done reading maxes
    #pragma unroll
    for (int mi = 0; mi < 2; mi++)
        #pragma unroll
        for (int h2 = 0; h2 < 2; h2++)
            if (tg == 0) s_red[warpN][warpM*32 + mi*16 + gID + h2*8] = psum[mi][h2];
    __syncthreads();
    if (warpN == 0 && tg == 0) {
        #pragma unroll
        for (int mi = 0; mi < 2; mi++)
            #pragma unroll
            for (int h2 = 0; h2 < 2; h2++) {
                int row = warpM*32 + mi*16 + gID + h2*8;
                float tot = s_red[0][row] + s_red[1][row] + s_red[2][row] + s_red[3][row];
                s_inv[row] = 1.0f / tot;
            }
    }

    // ---- pack P (unnormalized) into A-fragments, hi/lo ----
    uint32_t phi[2][4][4], plo[2][4][4];
    #pragma unroll
    for (int mi = 0; mi < 2; mi++)
        #pragma unroll
        for (int kk = 0; kk < 4; kk++)
            #pragma unroll
            for (int j = 0; j < 2; j++) {
                float* cc = acc[mi][kk*2+j];
                pksplit(cc[0], cc[1], phi[mi][kk][j*2+0], plo[mi][kk][j*2+0]);
                pksplit(cc[2], cc[3], phi[mi][kk][j*2+1], plo[mi][kk][j*2+1]);
            }

    // ---- O_partial = P(32 x 64-slice) * V(slice x 64d), via ldmatrix.trans on V ----
    float oacc[2][8][4];
    #pragma unroll
    for (int i = 0; i < 2; i++)
        #pragma unroll
        for (int j = 0; j < 8; j++)
            #pragma unroll
            for (int e = 0; e < 4; e++) oacc[i][j][e] = 0.f;
    {
        const int l8 = lane & 7, sel = lane >> 3;
        #pragma unroll
        for (int kk = 0; kk < 4; kk++) {
            #pragma unroll
            for (int ng = 0; ng < 4; ng++) {
                // trans read: address rows = key index (k), 16B = 8 d-cols
                int vrow = warpN*64 + kk*16 + (sel & 1)*8 + l8;
                int vcol = ng*16 + (sel >> 1)*8;
                uint32_t off = (uint32_t)((vrow*KP + vcol)*2);
                uint32_t bh[4], bl[4];
                ldsm4t(bh, smb + AT_VHI + off);
                ldsm4t(bl, smb + AT_VLO + off);
                #pragma unroll
                for (int mi = 0; mi < 2; mi++)
                    #pragma unroll
                    for (int j = 0; j < 2; j++) {
                        mma16816(oacc[mi][ng*2+j], phi[mi][kk], bh + j*2);
                        mma16816(oacc[mi][ng*2+j], phi[mi][kk], bl + j*2);
                        mma16816(oacc[mi][ng*2+j], plo[mi][kk], bh + j*2);
                    }
            }
        }
    }

    // ---- cross-warp reduce over the 4 key-slices (OP aliases dead K region) ----
    __syncthreads();   // K region dead; safe to overwrite
    float* op = (float*)(asm_ + AT_OP) + wid*2048;
    #pragma unroll
    for (int mi = 0; mi < 2; mi++)
        #pragma unroll
        for (int nd = 0; nd < 8; nd++) {
            int c = nd*8 + tg*2;
            op[(mi*16 + gID    )*64 + c    ] = oacc[mi][nd][0];
            op[(mi*16 + gID    )*64 + c + 1] = oacc[mi][nd][1];
            op[(mi*16 + gID + 8)*64 + c    ] = oacc[mi][nd][2];
            op[(mi*16 + gID + 8)*64 + c + 1] = oacc[mi][nd][3];
        }
    __syncthreads();
    for (int f = t; f < 1024; f += 256) {
        int R = f >> 4, c4 = (f & 15) * 4;
        int wg = (R >> 5) * 4;         // warpM group base wid
        const float* base0 = (const float*)(asm_ + AT_OP);
        float4 s = make_float4(0.f, 0.f, 0.f, 0.f);
        #pragma unroll
        for (int w = 0; w < 4; w++) {
            float4 v = *(const float4*)(base0 + (wg + w)*2048 + (R & 31)*64 + c4);
            s.x += v.x; s.y += v.y; s.z += v.z; s.w += v.w;
        }
        float inv = s_inv[R];
        s.x *= inv; s.y *= inv; s.z *= inv; s.w *= inv;
        *(float4*)(g_o + ((size_t)(b*N_) + q0 + R)*E_ + h*D_ + c4) = s;
    }
}

// ---------------- launcher ----------------
extern "C" void kernel_launch(void* const* d_in, const int* in_sizes, int n_in,
                              void* d_out, int out_size) {
    const float* x     = (const float*)d_in[0];
    const float* U     = (const float*)d_in[1];
    const float* w_qkv = (const float*)d_in[2];
    const float* b_qkv = (const float*)d_in[3];
    const float* w_out = (const float*)d_in[4];
    const float* b_out = (const float*)d_in[5];
    const float* w_u   = (const float*)d_in[6];
    const float* b_u   = (const float*)d_in[7];
    float* out = (float*)d_out;

    cudaFuncSetAttribute(gemm_mma, cudaFuncAttributeMaxDynamicSharedMemorySize, GEMM_SMEM);
    cudaFuncSetAttribute(attn_kernel, cudaFuncAttributeMaxDynamicSharedMemorySize, ATTN_SMEM);

    bias_kernel<<<(B_*N_*N_ + 255)/256, 256>>>(U, w_u, b_u);

    { dim3 g(1536/128, (B_*N_)/128); gemm_mma<<<g, 256, GEMM_SMEM>>>(x, w_qkv, b_qkv, 0, nullptr); }

    { dim3 g(B_*H_, N_/64); attn_kernel<<<g, 256, ATTN_SMEM>>>(); }

    { dim3 g(512/128, (B_*N_)/128); gemm_mma<<<g, 256, GEMM_SMEM>>>(nullptr, w_out, b_out, 1, out); }
}

// round 7
// speedup vs baseline: 2.5695x; 1.1397x over previous
#include <cuda_runtime.h>
#include <cuda_bf16.h>
#include <cstdint>
#include <math.h>

#define B_   32
#define N_   256
#define E_   512
#define H_   8
#define D_   64
#define ID_  8
#define KDIM 512

// ---------------- device-global scratch (alloc-free), all bf16 hi/lo ----------------
__device__ __nv_bfloat16 g_xhi[(size_t)B_*N_*E_],  g_xlo[(size_t)B_*N_*E_];
__device__ __nv_bfloat16 g_wqhi[(size_t)3*E_*E_],  g_wqlo[(size_t)3*E_*E_];
__device__ __nv_bfloat16 g_wohi[(size_t)E_*E_],    g_wolo[(size_t)E_*E_];
__device__ __nv_bfloat16 g_qhi[(size_t)B_*H_*N_*D_], g_qlo[(size_t)B_*H_*N_*D_];
__device__ __nv_bfloat16 g_khi[(size_t)B_*H_*N_*D_], g_klo[(size_t)B_*H_*N_*D_];
__device__ __nv_bfloat16 g_vhi[(size_t)B_*H_*N_*D_], g_vlo[(size_t)B_*H_*N_*D_];
__device__ __nv_bfloat16 g_ohi[(size_t)B_*N_*E_],  g_olo[(size_t)B_*N_*E_];
__device__ float g_bias[(size_t)B_*H_*N_*N_];

// ================= helpers =================
__device__ __forceinline__ uint32_t smem_u32(const void* p) {
    uint32_t a;
    asm("{ .reg .u64 t; cvta.to.shared.u64 t, %1; cvt.u32.u64 %0, t; }" : "=r"(a) : "l"(p));
    return a;
}
__device__ __forceinline__ void ldsm4(uint32_t* r, uint32_t addr) {
    asm volatile("ldmatrix.sync.aligned.m8n8.x4.shared.b16 {%0,%1,%2,%3}, [%4];"
        : "=r"(r[0]), "=r"(r[1]), "=r"(r[2]), "=r"(r[3]) : "r"(addr));
}
__device__ __forceinline__ void ldsm4t(uint32_t* r, uint32_t addr) {
    asm volatile("ldmatrix.sync.aligned.m8n8.x4.trans.shared.b16 {%0,%1,%2,%3}, [%4];"
        : "=r"(r[0]), "=r"(r[1]), "=r"(r[2]), "=r"(r[3]) : "r"(addr));
}
__device__ __forceinline__ void mma16816(float* c, const uint32_t* a, const uint32_t* b) {
    asm volatile("mma.sync.aligned.m16n8k16.row.col.f32.bf16.bf16.f32 "
        "{%0,%1,%2,%3}, {%4,%5,%6,%7}, {%8,%9}, {%0,%1,%2,%3};"
        : "+f"(c[0]), "+f"(c[1]), "+f"(c[2]), "+f"(c[3])
        : "r"(a[0]), "r"(a[1]), "r"(a[2]), "r"(a[3]), "r"(b[0]), "r"(b[1]));
}
__device__ __forceinline__ void split2(float x, float y,
                                       __nv_bfloat162& hi, __nv_bfloat162& lo) {
    __nv_bfloat16 hx = __float2bfloat16(x), hy = __float2bfloat16(y);
    hi.x = hx; hi.y = hy;
    lo.x = __float2bfloat16(x - __bfloat162float(hx));
    lo.y = __float2bfloat16(y - __bfloat162float(hy));
}
__device__ __forceinline__ void pksplit(float x, float y, uint32_t& hi, uint32_t& lo) {
    __nv_bfloat162 H, L;
    split2(x, y, H, L);
    hi = *reinterpret_cast<uint32_t*>(&H);
    lo = *reinterpret_cast<uint32_t*>(&L);
}
#define CP16(dst, src) asm volatile("cp.async.cg.shared.global [%0], [%1], 16;" :: "r"(dst), "l"(src))
#define CPCOMMIT()     asm volatile("cp.async.commit_group;" ::: "memory")
#define CPWAIT0()      asm volatile("cp.async.wait_group 0;" ::: "memory")

// ---------------- fp32 -> bf16 hi/lo pre-split ----------------
__global__ void conv_kernel(const float4* __restrict__ src, int n4, int which) {
    __nv_bfloat162* hi;
    __nv_bfloat162* lo;
    if      (which == 0) { hi = (__nv_bfloat162*)g_xhi;  lo = (__nv_bfloat162*)g_xlo; }
    else if (which == 1) { hi = (__nv_bfloat162*)g_wqhi; lo = (__nv_bfloat162*)g_wqlo; }
    else                 { hi = (__nv_bfloat162*)g_wohi; lo = (__nv_bfloat162*)g_wolo; }
    int idx = blockIdx.x * blockDim.x + threadIdx.x;
    if (idx >= n4) return;
    float4 v = src[idx];
    __nv_bfloat162 h0, l0, h1, l1;
    split2(v.x, v.y, h0, l0); split2(v.z, v.w, h1, l1);
    hi[idx*2] = h0; hi[idx*2+1] = h1;
    lo[idx*2] = l0; lo[idx*2+1] = l1;
}

// ---------------- bias = U @ w_u^T + b_u, transposed to [B,H,N,N] ----------------
__global__ void bias_kernel(const float* __restrict__ U,
                            const float* __restrict__ w_u,
                            const float* __restrict__ b_u) {
    __shared__ float sw[H_*ID_];
    __shared__ float sb[H_];
    if (threadIdx.x < H_*ID_) sw[threadIdx.x] = w_u[threadIdx.x];
    if (threadIdx.x < H_)     sb[threadIdx.x] = b_u[threadIdx.x];
    __syncthreads();
    int idx = blockIdx.x * blockDim.x + threadIdx.x;
    if (idx >= B_*N_*N_) return;
    const float4* up = (const float4*)(U + (size_t)idx * ID_);
    float4 u0 = up[0], u1 = up[1];
    float u[8] = {u0.x,u0.y,u0.z,u0.w,u1.x,u1.y,u1.z,u1.w};
    int b  = idx / (N_*N_);
    int nm = idx - b * (N_*N_);
    #pragma unroll
    for (int h = 0; h < H_; h++) {
        float s = sb[h];
        #pragma unroll
        for (int i = 0; i < 8; i++) s += u[i] * sw[h*ID_ + i];
        g_bias[((size_t)(b*H_ + h)) * (N_*N_) + nm] = s;
    }
}

// ============ HMMA GEMM on pre-split bf16: C = A * W^T, cp.async pipeline ============
// CTA 128x128, k-slab 32 (bf16), 8 warps (2x4) of 64x32 warp tiles, double buffered.
#define TK 32
#define NKS (KDIM/TK)        // 16
#define LDS_BF 40            // halfword stride (80 B rows, conflict-free ldmatrix)
#define MAT_B (128*LDS_BF*2) // 10240 B per matrix tile
#define STG_B (4*MAT_B)      // Ahi,Alo,Whi,Wlo = 40960
#define GEMM_SMEM (2*STG_B)  // 81920

__global__ __launch_bounds__(256, 2)
void gemm_mma(const float* __restrict__ bias, int mode, float* __restrict__ out) {
    extern __shared__ char dsm[];
    const int t    = threadIdx.x;
    const int lane = t & 31;
    const int wid  = t >> 5;
    const int warpM = wid >> 2;
    const int warpN = wid & 3;
    const int rowBase = blockIdx.y * 128;
    const int colBase = blockIdx.x * 128;
    const uint32_t smb = smem_u32(dsm);

    // device symbols resolved in device code (mode selects operand set)
    const __nv_bfloat16 *Ah, *Al, *Wh, *Wl;
    if (mode == 0) { Ah = g_xhi; Al = g_xlo; Wh = g_wqhi; Wl = g_wqlo; }
    else           { Ah = g_ohi; Al = g_olo; Wh = g_wohi; Wl = g_wolo; }

    float acc[4][4][4];
    #pragma unroll
    for (int i = 0; i < 4; i++)
        #pragma unroll
        for (int j = 0; j < 4; j++)
            #pragma unroll
            for (int e = 0; e < 4; e++) acc[i][j][e] = 0.f;

    // issue cp.async for slab s into stage s&1 (8 x 16B per thread)
    auto issue = [&](int s) {
        int k0 = s * TK;
        uint32_t st = smb + (s & 1)*STG_B;
        #pragma unroll
        for (int l = 0; l < 2; l++) {
            int f = t + l*256;            // 0..511
            int r = f >> 2, c = f & 3;    // row, 16B-chunk (4 per 64B row)
            uint32_t doff = (uint32_t)(r*80 + c*16);
            const __nv_bfloat16* ga = Ah + (size_t)(rowBase + r)*KDIM + k0 + c*8;
            const __nv_bfloat16* gl = Al + (size_t)(rowBase + r)*KDIM + k0 + c*8;
            const __nv_bfloat16* gw = Wh + (size_t)(colBase + r)*KDIM + k0 + c*8;
            const __nv_bfloat16* gx = Wl + (size_t)(colBase + r)*KDIM + k0 + c*8;
            CP16(st + doff,           ga);
            CP16(st + MAT_B + doff,   gl);
            CP16(st + 2*MAT_B + doff, gw);
            CP16(st + 3*MAT_B + doff, gx);
        }
    };

    issue(0);
    CPCOMMIT();

    for (int ks = 0; ks < NKS; ks++) {
        CPWAIT0();
        __syncthreads();
        if (ks + 1 < NKS) { issue(ks + 1); CPCOMMIT(); }

        uint32_t stg = smb + (ks & 1)*STG_B;
        #pragma unroll
        for (int k16 = 0; k16 < 2; k16++) {
            int colb = k16 * 16;
            uint32_t whi[4][2], wlo[4][2];
            {
                int l8  = lane & 7, sel = lane >> 3;
                #pragma unroll
                for (int np = 0; np < 2; np++) {
                    int wrow = warpN*32 + np*16 + (sel >> 1)*8 + l8;
                    int wcol = colb + (sel & 1)*8;
                    uint32_t off = (uint32_t)(wrow*80 + wcol*2);
                    uint32_t r[4];
                    ldsm4(r, stg + 2*MAT_B + off);
                    whi[np*2+0][0]=r[0]; whi[np*2+0][1]=r[1];
                    whi[np*2+1][0]=r[2]; whi[np*2+1][1]=r[3];
                    ldsm4(r, stg + 3*MAT_B + off);
                    wlo[np*2+0][0]=r[0]; wlo[np*2+0][1]=r[1];
                    wlo[np*2+1][0]=r[2]; wlo[np*2+1][1]=r[3];
                }
            }
            int r8 = lane & 7, half = (lane >> 3) & 1, kk = lane >> 4;
            #pragma unroll
            for (int mi = 0; mi < 4; mi++) {
                int arow = warpM*64 + mi*16 + half*8 + r8;
                int acol = colb + kk*8;
                uint32_t off = (uint32_t)(arow*80 + acol*2);
                uint32_t a[4];
                ldsm4(a, stg + off);
                #pragma unroll
                for (int ni = 0; ni < 4; ni++) mma16816(acc[mi][ni], a, whi[ni]);
                #pragma unroll
                for (int ni = 0; ni < 4; ni++) mma16816(acc[mi][ni], a, wlo[ni]);
                ldsm4(a, stg + MAT_B + off);
                #pragma unroll
                for (int ni = 0; ni < 4; ni++) mma16816(acc[mi][ni], a, whi[ni]);
            }
        }
        __syncthreads();
    }

    // epilogue: pairs (c, c+1) per e-half
    const int gID = lane >> 2, tg = lane & 3;
    #pragma unroll
    for (int mi = 0; mi < 4; mi++) {
        #pragma unroll
        for (int ni = 0; ni < 4; ni++) {
            #pragma unroll
            for (int e2 = 0; e2 < 2; e2++) {
                int r = rowBase + warpM*64 + mi*16 + gID + e2*8;
                int c = colBase + warpN*32 + ni*8 + tg*2;
                float v0 = acc[mi][ni][e2*2+0] + __ldg(bias + c);
                float v1 = acc[mi][ni][e2*2+1] + __ldg(bias + c + 1);
                if (mode == 0) {
                    int bb = r >> 8, n = r & 255;
                    int sec = c >> 9;
                    int jj  = c & 511;
                    int h = jj >> 6, d = jj & 63;
                    size_t dst = ((size_t)((bb*H_ + h)*N_ + n))*D_ + d;
                    __nv_bfloat162 hi, lo;
                    if (sec == 0) {
                        split2(v0 * 0.125f, v1 * 0.125f, hi, lo);
                        *(__nv_bfloat162*)(g_qhi + dst) = hi;
                        *(__nv_bfloat162*)(g_qlo + dst) = lo;
                    } else if (sec == 1) {
                        split2(v0, v1, hi, lo);
                        *(__nv_bfloat162*)(g_khi + dst) = hi;
                        *(__nv_bfloat162*)(g_klo + dst) = lo;
                    } else {
                        split2(v0, v1, hi, lo);
                        *(__nv_bfloat162*)(g_vhi + dst) = hi;
                        *(__nv_bfloat162*)(g_vlo + dst) = lo;
                    }
                } else {
                    out[(size_t)r*E_ + c]     = v0;
                    out[(size_t)r*E_ + c + 1] = v1;
                }
            }
        }
    }
}

// ======== attention: HMMA, register softmax; loads pre-split bf16 ========
#define KP 72
#define AT_KHI 0
#define AT_KLO 36864
#define AT_QHI 73728
#define AT_QLO 82944
#define AT_VHI 92160
#define AT_VLO 129024
#define AT_OP  0
#define ATTN_SMEM 165888

__global__ __launch_bounds__(256)
void attn_kernel() {
    extern __shared__ char asm_[];
    __shared__ float s_red[4][64];
    __shared__ float s_inv[64];

    const int bh = blockIdx.x;
    const int q0 = blockIdx.y << 6;
    const int t  = threadIdx.x;
    const int lane = t & 31;
    const int wid  = t >> 5;
    const int warpM = wid >> 2;
    const int warpN = wid & 3;
    const int gID = lane >> 2, tg = lane & 3;
    const int b  = bh >> 3, h = bh & 7;
    const uint32_t smb = smem_u32(asm_);

    const uint4* khi = (const uint4*)(g_khi + (size_t)bh * N_ * D_);
    const uint4* klo = (const uint4*)(g_klo + (size_t)bh * N_ * D_);
    const uint4* vhi = (const uint4*)(g_vhi + (size_t)bh * N_ * D_);
    const uint4* vlo = (const uint4*)(g_vlo + (size_t)bh * N_ * D_);
    const uint4* qhi = (const uint4*)(g_qhi + (size_t)bh * N_ * D_ + (size_t)q0 * D_);
    const uint4* qlo = (const uint4*)(g_qlo + (size_t)bh * N_ * D_ + (size_t)q0 * D_);
    const float* bbase = g_bias + (size_t)bh * N_ * N_;

    // ---- pure 16B copies into padded smem (8 bf16 per chunk) ----
    for (int f = t; f < 2048; f += 256) {
        int row = f >> 3, c8 = f & 7;
        int off = row*144 + c8*16;
        *(uint4*)(asm_ + AT_KHI + off) = khi[f];
        *(uint4*)(asm_ + AT_KLO + off) = klo[f];
        *(uint4*)(asm_ + AT_VHI + off) = vhi[f];
        *(uint4*)(asm_ + AT_VLO + off) = vlo[f];
    }
    for (int f = t; f < 512; f += 256) {
        int row = f >> 3, c8 = f & 7;
        int off = row*144 + c8*16;
        *(uint4*)(asm_ + AT_QHI + off) = qhi[f];
        *(uint4*)(asm_ + AT_QLO + off) = qlo[f];
    }
    __syncthreads();

    // ---- S = Q K^T (warp tile 32 rows x 64 keys), 3-term bf16 split ----
    float acc[2][8][4];
    #pragma unroll
    for (int i = 0; i < 2; i++)
        #pragma unroll
        for (int j = 0; j < 8; j++)
            #pragma unroll
            for (int e = 0; e < 4; e++) acc[i][j][e] = 0.f;
    {
        const int l8 = lane & 7, sel = lane >> 3;
        const int r8 = lane & 7, halfq = (lane >> 3) & 1, k8 = lane >> 4;
        #pragma unroll
        for (int kk = 0; kk < 4; kk++) {
            uint32_t bhi[8][2], blo[8][2];
            #pragma unroll
            for (int np = 0; np < 4; np++) {
                int wrow = warpN*64 + np*16 + (sel >> 1)*8 + l8;
                int wcol = kk*16 + (sel & 1)*8;
                uint32_t off = (uint32_t)((wrow*KP + wcol)*2);
                uint32_t r[4];
                ldsm4(r, smb + AT_KHI + off);
                bhi[np*2+0][0]=r[0]; bhi[np*2+0][1]=r[1];
                bhi[np*2+1][0]=r[2]; bhi[np*2+1][1]=r[3];
                ldsm4(r, smb + AT_KLO + off);
                blo[np*2+0][0]=r[0]; blo[np*2+0][1]=r[1];
                blo[np*2+1][0]=r[2]; blo[np*2+1][1]=r[3];
            }
            #pragma unroll
            for (int mi = 0; mi < 2; mi++) {
                int arow = warpM*32 + mi*16 + halfq*8 + r8;
                int acol = kk*16 + k8*8;
                uint32_t off = (uint32_t)((arow*KP + acol)*2);
                uint32_t a[4];
                ldsm4(a, smb + AT_QHI + off);
                #pragma unroll
                for (int nj = 0; nj < 8; nj++) mma16816(acc[mi][nj], a, bhi[nj]);
                #pragma unroll
                for (int nj = 0; nj < 8; nj++) mma16816(acc[mi][nj], a, blo[nj]);
                ldsm4(a, smb + AT_QLO + off);
                #pragma unroll
                for (int nj = 0; nj < 8; nj++) mma16816(acc[mi][nj], a, bhi[nj]);
            }
        }
    }

    // ---- add bias ----
    #pragma unroll
    for (int mi = 0; mi < 2; mi++) {
        int r0 = q0 + warpM*32 + mi*16 + gID;
        #pragma unroll
        for (int nj = 0; nj < 8; nj++) {
            int c = warpN*64 + nj*8 + tg*2;
            float2 b0 = *(const float2*)(bbase + (size_t)r0*N_ + c);
            float2 b1 = *(const float2*)(bbase + (size_t)(r0+8)*N_ + c);
            acc[mi][nj][0] += b0.x; acc[mi][nj][1] += b0.y;
            acc[mi][nj][2] += b1.x; acc[mi][nj][3] += b1.y;
        }
    }

    // ---- softmax on fragments ----
    #pragma unroll
    for (int mi = 0; mi < 2; mi++)
        #pragma unroll
        for (int h2 = 0; h2 < 2; h2++) {
            float m = -1e30f;
            #pragma unroll
            for (int nj = 0; nj < 8; nj++) {
                m = fmaxf(m, acc[mi][nj][h2*2+0]);
                m = fmaxf(m, acc[mi][nj][h2*2+1]);
            }
            m = fmaxf(m, __shfl_xor_sync(0xffffffffu, m, 1));
            m = fmaxf(m, __shfl_xor_sync(0xffffffffu, m, 2));
            if (tg == 0) s_red[warpN][warpM*32 + mi*16 + gID + h2*8] = m;
        }
    __syncthreads();
    float psum[2][2];
    #pragma unroll
    for (int mi = 0; mi < 2; mi++)
        #pragma unroll
        for (int h2 = 0; h2 < 2; h2++) {
            int row = warpM*32 + mi*16 + gID + h2*8;
            float fm = fmaxf(fmaxf(s_red[0][row], s_red[1][row]),
                             fmaxf(s_red[2][row], s_red[3][row]));
            float s = 0.f;
            #pragma unroll
            for (int nj = 0; nj < 8; nj++) {
                float p0 = __expf(acc[mi][nj][h2*2+0] - fm);
                float p1 = __expf(acc[mi][nj][h2*2+1] - fm);
                acc[mi][nj][h2*2+0] = p0; acc[mi][nj][h2*2+1] = p1;
                s += p0 + p1;
            }
            s += __shfl_xor_sync(0xffffffffu, s, 1);
            s += __shfl_xor_sync(0xffffffffu, s, 2);
            psum[mi][h2] = s;
        }
    __syncthreads();
    #pragma unroll
    for (int mi = 0; mi < 2; mi++)
        #pragma unroll
        for (int h2 = 0; h2 < 2; h2++)
            if (tg == 0) s_red[warpN][warpM*32 + mi*16 + gID + h2*8] = psum[mi][h2];
    __syncthreads();
    if (warpN == 0 && tg == 0) {
        #pragma unroll
        for (int mi = 0; mi < 2; mi++)
            #pragma unroll
            for (int h2 = 0; h2 < 2; h2++) {
                int row = warpM*32 + mi*16 + gID + h2*8;
                float tot = s_red[0][row] + s_red[1][row] + s_red[2][row] + s_red[3][row];
                s_inv[row] = 1.0f / tot;
            }
    }

    // ---- pack P into A-fragments, hi/lo ----
    uint32_t phi[2][4][4], plo[2][4][4];
    #pragma unroll
    for (int mi = 0; mi < 2; mi++)
        #pragma unroll
        for (int kk = 0; kk < 4; kk++)
            #pragma unroll
            for (int j = 0; j < 2; j++) {
                float* cc = acc[mi][kk*2+j];
                pksplit(cc[0], cc[1], phi[mi][kk][j*2+0], plo[mi][kk][j*2+0]);
                pksplit(cc[2], cc[3], phi[mi][kk][j*2+1], plo[mi][kk][j*2+1]);
            }

    // ---- O_partial = P * V (ldmatrix.trans on V) ----
    float oacc[2][8][4];
    #pragma unroll
    for (int i = 0; i < 2; i++)
        #pragma unroll
        for (int j = 0; j < 8; j++)
            #pragma unroll
            for (int e = 0; e < 4; e++) oacc[i][j][e] = 0.f;
    {
        const int l8 = lane & 7, sel = lane >> 3;
        #pragma unroll
        for (int kk = 0; kk < 4; kk++) {
            #pragma unroll
            for (int ng = 0; ng < 4; ng++) {
                int vrow = warpN*64 + kk*16 + (sel & 1)*8 + l8;
                int vcol = ng*16 + (sel >> 1)*8;
                uint32_t off = (uint32_t)((vrow*KP + vcol)*2);
                uint32_t bh[4], bl[4];
                ldsm4t(bh, smb + AT_VHI + off);
                ldsm4t(bl, smb + AT_VLO + off);
                #pragma unroll
                for (int mi = 0; mi < 2; mi++)
                    #pragma unroll
                    for (int j = 0; j < 2; j++) {
                        mma16816(oacc[mi][ng*2+j], phi[mi][kk], bh + j*2);
                        mma16816(oacc[mi][ng*2+j], phi[mi][kk], bl + j*2);
                        mma16816(oacc[mi][ng*2+j], plo[mi][kk], bh + j*2);
                    }
            }
        }
    }

    // ---- cross-warp reduce, normalize, write o as bf16 hi/lo ----
    __syncthreads();
    float* op = (float*)(asm_ + AT_OP) + wid*2048;
    #pragma unroll
    for (int mi = 0; mi < 2; mi++)
        #pragma unroll
        for (int nd = 0; nd < 8; nd++) {
            int c = nd*8 + tg*2;
            op[(mi*16 + gID    )*64 + c    ] = oacc[mi][nd][0];
            op[(mi*16 + gID    )*64 + c + 1] = oacc[mi][nd][1];
            op[(mi*16 + gID + 8)*64 + c    ] = oacc[mi][nd][2];
            op[(mi*16 + gID + 8)*64 + c + 1] = oacc[mi][nd][3];
        }
    __syncthreads();
    for (int f = t; f < 1024; f += 256) {
        int R = f >> 4, c4 = (f & 15) * 4;
        int wg = (R >> 5) * 4;
        const float* base0 = (const float*)(asm_ + AT_OP);
        float4 s = make_float4(0.f, 0.f, 0.f, 0.f);
        #pragma unroll
        for (int w = 0; w < 4; w++) {
            float4 v = *(const float4*)(base0 + (wg + w)*2048 + (R & 31)*64 + c4);
            s.x += v.x; s.y += v.y; s.z += v.z; s.w += v.w;
        }
        float inv = s_inv[R];
        s.x *= inv; s.y *= inv; s.z *= inv; s.w *= inv;
        __nv_bfloat162 h0, l0, h1, l1;
        split2(s.x, s.y, h0, l0); split2(s.z, s.w, h1, l1);
        size_t dst = ((size_t)(b*N_) + q0 + R)*E_ + h*D_ + c4;
        *(__nv_bfloat162*)(g_ohi + dst)     = h0;
        *(__nv_bfloat162*)(g_ohi + dst + 2) = h1;
        *(__nv_bfloat162*)(g_olo + dst)     = l0;
        *(__nv_bfloat162*)(g_olo + dst + 2) = l1;
    }
}

// ---------------- launcher ----------------
extern "C" void kernel_launch(void* const* d_in, const int* in_sizes, int n_in,
                              void* d_out, int out_size) {
    const float* x     = (const float*)d_in[0];
    const float* U     = (const float*)d_in[1];
    const float* w_qkv = (const float*)d_in[2];
    const float* b_qkv = (const float*)d_in[3];
    const float* w_out = (const float*)d_in[4];
    const float* b_out = (const float*)d_in[5];
    const float* w_u   = (const float*)d_in[6];
    const float* b_u   = (const float*)d_in[7];
    float* out = (float*)d_out;

    cudaFuncSetAttribute(gemm_mma, cudaFuncAttributeMaxDynamicSharedMemorySize, GEMM_SMEM);
    cudaFuncSetAttribute(attn_kernel, cudaFuncAttributeMaxDynamicSharedMemorySize, ATTN_SMEM);

    // pre-split fp32 -> bf16 hi/lo
    conv_kernel<<<(B_*N_*E_/4 + 255)/256, 256>>>((const float4*)x, B_*N_*E_/4, 0);
    conv_kernel<<<(3*E_*E_/4 + 255)/256, 256>>>((const float4*)w_qkv, 3*E_*E_/4, 1);
    conv_kernel<<<(E_*E_/4 + 255)/256, 256>>>((const float4*)w_out, E_*E_/4, 2);

    bias_kernel<<<(B_*N_*N_ + 255)/256, 256>>>(U, w_u, b_u);

    { dim3 g(1536/128, (B_*N_)/128); gemm_mma<<<g, 256, GEMM_SMEM>>>(b_qkv, 0, nullptr); }

    { dim3 g(B_*H_, N_/64); attn_kernel<<<g, 256, ATTN_SMEM>>>(); }

    { dim3 g(512/128, (B_*N_)/128); gemm_mma<<<g, 256, GEMM_SMEM>>>(b_out, 1, out); }
}